// round 9
// baseline (speedup 1.0000x reference)
#include <cuda_runtime.h>
#include <cstdint>

#define SEQ   2048
#define DM    2048
#define NH    32
#define DH    64
#define CK    128
#define NC    16
#define BZ    4
#define MROWS (BZ*SEQ)   // 8192
#define BK    16
#define NKT   (DM/BK)    // 128

// ---------------- scratch (device globals; no allocation) ----------------
__device__ float g_rx [BZ*SEQ*DM];
__device__ float g_kx [BZ*SEQ*DM];
__device__ float g_vx [BZ*SEQ*DM];
__device__ float g_r  [BZ*SEQ*DM];
__device__ float g_k  [BZ*SEQ*DM];
__device__ float g_v  [BZ*SEQ*DM];
__device__ float g_att[BZ*SEQ*DM];
__device__ float g_rkw[(size_t)BZ*NC*NH*CK*CK];
__device__ float g_kv   [BZ*NH*NC*DH*DH];
__device__ float g_state[BZ*NH*NC*DH*DH];
__device__ float g_wtr[DM*DM];
__device__ float g_wtk[DM*DM];
__device__ float g_wtv[DM*DM];
__device__ float g_wto[DM*DM];

// ---------------- small PTX helpers ----------------
__device__ __forceinline__ unsigned f2tf(float v)
{
    unsigned r;
    asm("cvt.rna.tf32.f32 %0, %1;" : "=r"(r) : "f"(v));
    return r;
}
__device__ __forceinline__ float roundtf(float v) { return __uint_as_float(f2tf(v)); }

__device__ __forceinline__ uint32_t smem_u32(const void* p)
{
    uint32_t a;
    asm("{ .reg .u64 t; cvta.to.shared.u64 t, %1; cvt.u32.u64 %0, t; }" : "=r"(a) : "l"(p));
    return a;
}
template<int N> __device__ __forceinline__ void cp_wait()
{
    asm volatile("cp.async.wait_group %0;" :: "n"(N) : "memory");
}
__device__ __forceinline__ void cp16(uint32_t dst, const void* src)
{
    asm volatile("cp.async.cg.shared.global [%0], [%1], 16;" :: "r"(dst), "l"(src));
}
__device__ __forceinline__ void cp_commit()
{
    asm volatile("cp.async.commit_group;" ::: "memory");
}
__device__ __forceinline__ void mma_tf32(float* c, const unsigned* a, const unsigned* b)
{
    asm volatile(
        "mma.sync.aligned.m16n8k8.row.col.f32.tf32.tf32.f32 "
        "{%0,%1,%2,%3}, {%4,%5,%6,%7}, {%8,%9}, {%0,%1,%2,%3};"
        : "+f"(c[0]), "+f"(c[1]), "+f"(c[2]), "+f"(c[3])
        : "r"(a[0]), "r"(a[1]), "r"(a[2]), "r"(a[3]),
          "r"(b[0]), "r"(b[1]));
}
__device__ __forceinline__ void ldsm4(unsigned* r, uint32_t addr)
{
    asm volatile("ldmatrix.sync.aligned.m8n8.x4.shared.b16 {%0,%1,%2,%3}, [%4];"
        : "=r"(r[0]), "=r"(r[1]), "=r"(r[2]), "=r"(r[3]) : "r"(addr));
}

// ---------------- fused LN + token-shift mixing ----------------
__global__ void lnmix_kernel(const float* __restrict__ x,
                             const float* __restrict__ sc,
                             const float* __restrict__ bi,
                             const float* __restrict__ tmr,
                             const float* __restrict__ tmk,
                             const float* __restrict__ tmv,
                             float* __restrict__ xlast)
{
    int row = blockIdx.x;
    int t   = row & (SEQ - 1);
    const float* xr = x + (size_t)row * DM;
    float cur[8], prv[8];
    float s0 = 0.f, q0 = 0.f, s1 = 0.f, q1 = 0.f;
#pragma unroll
    for (int i = 0; i < 8; i++) {
        int c = threadIdx.x + i * 256;
        float v = xr[c];
        cur[i] = v; s0 += v; q0 += v * v;
        float u = t ? xr[c - DM] : 0.f;
        prv[i] = u; s1 += u; q1 += u * u;
    }
#pragma unroll
    for (int o = 16; o > 0; o >>= 1) {
        s0 += __shfl_xor_sync(0xffffffffu, s0, o);
        q0 += __shfl_xor_sync(0xffffffffu, q0, o);
        s1 += __shfl_xor_sync(0xffffffffu, s1, o);
        q1 += __shfl_xor_sync(0xffffffffu, q1, o);
    }
    __shared__ float rs0[8], rq0[8], rs1[8], rq1[8];
    int w = threadIdx.x >> 5;
    if ((threadIdx.x & 31) == 0) { rs0[w] = s0; rq0[w] = q0; rs1[w] = s1; rq1[w] = q1; }
    __syncthreads();
    s0 = 0.f; q0 = 0.f; s1 = 0.f; q1 = 0.f;
#pragma unroll
    for (int i = 0; i < 8; i++) { s0 += rs0[i]; q0 += rq0[i]; s1 += rs1[i]; q1 += rq1[i]; }
    float mu0  = s0 * (1.f / DM);
    float inv0 = rsqrtf(q0 * (1.f / DM) - mu0 * mu0 + 1e-5f);
    float mu1  = s1 * (1.f / DM);
    float inv1 = rsqrtf(q1 * (1.f / DM) - mu1 * mu1 + 1e-5f);
    bool last = (t == SEQ - 1);
#pragma unroll
    for (int i = 0; i < 8; i++) {
        int c = threadIdx.x + i * 256;
        float yc = (cur[i] - mu0) * inv0 * sc[c] + bi[c];
        float yp = t ? (prv[i] - mu1) * inv1 * sc[c] + bi[c] : 0.f;
        size_t off = (size_t)row * DM + c;
        float mr = tmr[c], mk = tmk[c], mv = tmv[c];
        g_rx[off] = roundtf(yc * mr + (1.f - mr) * yp);
        g_kx[off] = roundtf(yc * mk + (1.f - mk) * yp);
        g_vx[off] = roundtf(yc * mv + (1.f - mv) * yp);
        if (last) xlast[(row >> 11) * DM + c] = yc;
    }
}

// ---------------- 4 weight transposes in one launch (tf32 rounding) --------
__global__ void transpose4_kernel(const float* __restrict__ s0, float* __restrict__ d0,
                                  const float* __restrict__ s1, float* __restrict__ d1,
                                  const float* __restrict__ s2, float* __restrict__ d2,
                                  const float* __restrict__ s3, float* __restrict__ d3)
{
    const float* src; float* dst;
    switch (blockIdx.z) {
        case 0:  src = s0; dst = d0; break;
        case 1:  src = s1; dst = d1; break;
        case 2:  src = s2; dst = d2; break;
        default: src = s3; dst = d3; break;
    }
    __shared__ float t[32][33];
    int bx = blockIdx.x * 32, by = blockIdx.y * 32;
#pragma unroll
    for (int i = 0; i < 4; i++)
        t[threadIdx.y + i * 8][threadIdx.x] =
            src[(size_t)(by + threadIdx.y + i * 8) * DM + bx + threadIdx.x];
    __syncthreads();
#pragma unroll
    for (int i = 0; i < 4; i++)
        dst[(size_t)(bx + threadIdx.y + i * 8) * DM + by + threadIdx.x] =
            roundtf(t[threadIdx.x][threadIdx.y + i * 8]);
}

// ---------------- tf32 mma.sync GEMM, 4 warps x 64x64 warp tiles ----------
// 128 threads, block tile 128x128x16, warp grid 2(m) x 2(n)
#define ASTRIDE 20                      // floats per smem row (16 data + 4 pad)
#define STG_FLOATS (2 * 128 * ASTRIDE)  // A tile + B tile per stage = 5120 floats

template<int MODE>
__global__ void __launch_bounds__(128, 2) tgemm_kernel(const float* __restrict__ Bt,
                                                       const float* __restrict__ Add,
                                                       float* __restrict__ Out)
{
    const float* A;
    float* C;
    if constexpr (MODE == 0) { A = g_rx; C = g_r; }
    else if constexpr (MODE == 1) { A = g_kx; C = g_k; }
    else if constexpr (MODE == 2) { A = g_vx; C = g_v; }
    else { A = g_att; C = Out; }

    extern __shared__ float smem[];
    uint32_t sb = smem_u32(smem);
    int tid = threadIdx.x, lane = tid & 31, warp = tid >> 5;
    int r0 = lane >> 2, c0 = lane & 3;
    int wm = (warp >> 1) * 64, wn = (warp & 1) * 64;
    int bm = blockIdx.y * 128, bn = blockIdx.x * 128;

    const float* Ag = A  + (size_t)bm * DM;
    const float* Bg = Bt + (size_t)bn * DM;

    // ldmatrix per-lane row addresses (byte offsets into tile)
    int lane7 = lane & 7;
    uint32_t a_off = (uint32_t)(((wm + ((lane >> 3) & 1) * 8 + lane7) * ASTRIDE
                                + (lane >> 4) * 4) * 4);
    uint32_t b_off = (uint32_t)(((wn + (lane >> 4) * 8 + lane7) * ASTRIDE
                                + ((lane >> 3) & 1) * 4) * 4);

    // copy: each thread owns one row of A and one row of B (4 cp16 each)
    auto copy_stage = [&](int buf, int kt) {
        uint32_t sA = sb + buf * (STG_FLOATS * 4);
        uint32_t sB = sA + 128 * ASTRIDE * 4;
        const float* Ac = Ag + kt * BK + (size_t)tid * DM;
        const float* Bc = Bg + kt * BK + (size_t)tid * DM;
        uint32_t off = tid * (ASTRIDE * 4);
#pragma unroll
        for (int q = 0; q < 4; q++) {
            cp16(sA + off + q * 16, Ac + q * 4);
            cp16(sB + off + q * 16, Bc + q * 4);
        }
        cp_commit();
    };

    float acc[4][8][4];
#pragma unroll
    for (int i = 0; i < 4; i++)
#pragma unroll
        for (int j = 0; j < 8; j++)
#pragma unroll
            for (int e = 0; e < 4; e++) acc[i][j][e] = 0.f;

    copy_stage(0, 0);
    copy_stage(1, 1);
    copy_stage(2, 2);
    cp_wait<2>();
    __syncthreads();

    for (int kt = 0; kt < NKT; kt++) {
        int buf = kt & 3;
        uint32_t sA = sb + buf * (STG_FLOATS * 4);
        uint32_t sB = sA + 128 * ASTRIDE * 4;
#pragma unroll
        for (int ks = 0; ks < 2; ks++) {
            uint32_t kb = ks * 32;               // k0 * 4 bytes
            unsigned af[4][4], bf[8][2];
#pragma unroll
            for (int i = 0; i < 4; i++)
                ldsm4(af[i], sA + a_off + i * (16 * ASTRIDE * 4) + kb);
#pragma unroll
            for (int jj = 0; jj < 4; jj++)
                ldsm4(&bf[jj * 2][0], sB + b_off + jj * (16 * ASTRIDE * 4) + kb);
#pragma unroll
            for (int i = 0; i < 4; i++)
#pragma unroll
                for (int j = 0; j < 8; j++)
                    mma_tf32(acc[i][j], af[i], bf[j]);
        }
        if (kt + 3 < NKT) copy_stage((kt + 3) & 3, kt + 3);
        else              cp_commit();
        cp_wait<2>();
        __syncthreads();
    }

#pragma unroll
    for (int i = 0; i < 4; i++) {
        int row = bm + wm + i * 16 + r0;
#pragma unroll
        for (int j = 0; j < 8; j++) {
            int col = bn + wn + j * 8 + c0 * 2;
            size_t o0 = (size_t)row * DM + col;
            size_t o1 = (size_t)(row + 8) * DM + col;
            float2 v0 = make_float2(acc[i][j][0], acc[i][j][1]);
            float2 v1 = make_float2(acc[i][j][2], acc[i][j][3]);
            if constexpr (MODE == 3) {
                float2 a0 = *(const float2*)(Add + o0);
                float2 a1 = *(const float2*)(Add + o1);
                v0.x += a0.x; v0.y += a0.y;
                v1.x += a1.x; v1.y += a1.y;
            }
            *(float2*)(C + o0) = v0;
            *(float2*)(C + o1) = v1;
        }
    }
}

// ---------------- rkw = (r @ k^T) * mask, per (b,chunk,head), 64x64 tiles --
__global__ void rkw_kernel(const float* __restrict__ tdcy,
                           const float* __restrict__ tfirst)
{
    int jt = blockIdx.x, it = blockIdx.y, bch = blockIdx.z;
    int h = bch & 31;
    int chunk = (bch >> 5) & 15;
    int b = bch >> 9;
    __shared__ float rs[64][68];
    __shared__ float ks[64][68];
    int tid = threadIdx.x;
    int lrow = tid >> 2;
    int lc4  = (tid & 3) * 16;
    size_t rbase = ((size_t)(b*SEQ + chunk*CK + it*64 + lrow)) * DM + h*64 + lc4;
    size_t kbase = ((size_t)(b*SEQ + chunk*CK + jt*64 + lrow)) * DM + h*64 + lc4;
#pragma unroll
    for (int m = 0; m < 4; m++) {
        float4 rv = *(const float4*)(g_r + rbase + m * 4);
        float4 kv = *(const float4*)(g_k + kbase + m * 4);
        int d = lc4 + m * 4;
        rs[d+0][lrow] = rv.x; rs[d+1][lrow] = rv.y; rs[d+2][lrow] = rv.z; rs[d+3][lrow] = rv.w;
        ks[d+0][lrow] = kv.x; ks[d+1][lrow] = kv.y; ks[d+2][lrow] = kv.z; ks[d+3][lrow] = kv.w;
    }
    __syncthreads();
    int tx = tid & 15, ty = tid >> 4;
    float acc[4][4] = {};
#pragma unroll 8
    for (int d = 0; d < 64; d++) {
        float4 a = *(const float4*)&rs[d][ty * 4];
        float4 bq = *(const float4*)&ks[d][tx * 4];
        float ar[4] = {a.x,a.y,a.z,a.w};
        float br[4] = {bq.x,bq.y,bq.z,bq.w};
#pragma unroll
        for (int x = 0; x < 4; x++)
#pragma unroll
            for (int y = 0; y < 4; y++)
                acc[x][y] += ar[x] * br[y];
    }
    float logw = -expf(tdcy[h]);
    float u    =  expf(tfirst[h]);
#pragma unroll
    for (int x = 0; x < 4; x++)
#pragma unroll
        for (int y = 0; y < 4; y++) {
            int i = it * 64 + ty * 4 + x;
            int j = jt * 64 + tx * 4 + y;
            float m;
            if (i > j)      m = expf(logw * (float)(i - j - 1));
            else if (i == j) m = u;
            else             m = 0.f;
            g_rkw[((size_t)bch * CK + i) * CK + j] = acc[x][y] * m;
        }
}

// ---------------- sep = rkw @ v, per (b,chunk,head) ----------------
__global__ void sep_kernel()
{
    int bch = blockIdx.x;
    int h = bch & 31;
    int chunk = (bch >> 5) & 15;
    int b = bch >> 9;
    int tid = threadIdx.x;
    __shared__ float vs[128][64];
    __shared__ float rk[16][132];
    {
        int row = tid >> 1, e0 = (tid & 1) * 32;
        size_t base = ((size_t)(b*SEQ + chunk*CK + row)) * DM + h*64 + e0;
#pragma unroll
        for (int m = 0; m < 8; m++)
            *(float4*)&vs[row][e0 + m * 4] = *(const float4*)(g_v + base + m * 4);
    }
    int ty = tid >> 3, tx = tid & 7;
    float acc[4][8] = {};
    int rrow = tid >> 1, jc = (tid & 1) * 8;
    for (int s = 0; s < 8; s++) {
        const float* src = g_rkw + ((size_t)bch * CK + rrow) * CK + s * 16 + jc;
        float4 r0 = *(const float4*)src;
        float4 r1 = *(const float4*)(src + 4);
        __syncthreads();
        rk[jc+0][rrow] = r0.x; rk[jc+1][rrow] = r0.y; rk[jc+2][rrow] = r0.z; rk[jc+3][rrow] = r0.w;
        rk[jc+4][rrow] = r1.x; rk[jc+5][rrow] = r1.y; rk[jc+6][rrow] = r1.z; rk[jc+7][rrow] = r1.w;
        __syncthreads();
#pragma unroll
        for (int jj = 0; jj < 16; jj++) {
            float4 a  = *(const float4*)&rk[jj][ty * 4];
            float4 b0 = *(const float4*)&vs[s * 16 + jj][tx * 8];
            float4 b1 = *(const float4*)&vs[s * 16 + jj][tx * 8 + 4];
            float ar[4] = {a.x,a.y,a.z,a.w};
            float br[8] = {b0.x,b0.y,b0.z,b0.w,b1.x,b1.y,b1.z,b1.w};
#pragma unroll
            for (int x = 0; x < 4; x++)
#pragma unroll
                for (int e = 0; e < 8; e++)
                    acc[x][e] += ar[x] * br[e];
        }
    }
    size_t obase = ((size_t)(b*SEQ + chunk*CK)) * DM + h*64;
#pragma unroll
    for (int x = 0; x < 4; x++) {
        size_t ro = obase + (size_t)(ty * 4 + x) * DM + tx * 8;
        float4 o0, o1;
        o0.x = acc[x][0]; o0.y = acc[x][1]; o0.z = acc[x][2]; o0.w = acc[x][3];
        o1.x = acc[x][4]; o1.y = acc[x][5]; o1.z = acc[x][6]; o1.w = acc[x][7];
        *(float4*)(g_att + ro)     = o0;
        *(float4*)(g_att + ro + 4) = o1;
    }
}

// ---------------- scan decomposition ----------------
__global__ void kv_kernel(const float* __restrict__ tdcy)
{
    int c = blockIdx.x, bh = blockIdx.y;
    int h = bh & 31, b = bh >> 5;
    int tid = threadIdx.x;
    __shared__ float bufA[32][68];
    __shared__ float bufB[32][68];
    float logw = -expf(tdcy[h]);
    int lrow = tid >> 3, lcol = (tid & 7) * 8;
    int td = (tid >> 4) * 4, te2 = (tid & 15) * 4;
    size_t base = ((size_t)(b*SEQ + c*CK)) * DM + h * 64;
    float sacc[4][4] = {};
    for (int s4 = 0; s4 < 4; s4++) {
        int j = s4 * 32 + lrow;
        float wk = expf(logw * (float)(127 - j));
        const float* ksrc = g_k + base + (size_t)j * DM + lcol;
        const float* vsrc = g_v + base + (size_t)j * DM + lcol;
        float4 k0 = *(const float4*)ksrc;
        float4 k1 = *(const float4*)(ksrc + 4);
        float4 w0 = *(const float4*)vsrc;
        float4 w1 = *(const float4*)(vsrc + 4);
        k0.x *= wk; k0.y *= wk; k0.z *= wk; k0.w *= wk;
        k1.x *= wk; k1.y *= wk; k1.z *= wk; k1.w *= wk;
        *(float4*)&bufA[lrow][lcol]     = k0;
        *(float4*)&bufA[lrow][lcol + 4] = k1;
        *(float4*)&bufB[lrow][lcol]     = w0;
        *(float4*)&bufB[lrow][lcol + 4] = w1;
        __syncthreads();
#pragma unroll 4
        for (int jj = 0; jj < 32; jj++) {
            float4 ka = *(const float4*)&bufA[jj][td];
            float4 vb = *(const float4*)&bufB[jj][te2];
            float ar[4] = {ka.x,ka.y,ka.z,ka.w};
            float br[4] = {vb.x,vb.y,vb.z,vb.w};
#pragma unroll
            for (int x = 0; x < 4; x++)
#pragma unroll
                for (int y = 0; y < 4; y++)
                    sacc[x][y] += ar[x] * br[y];
        }
        __syncthreads();
    }
    size_t obase = ((size_t)bh * NC + c) * 4096;
#pragma unroll
    for (int x = 0; x < 4; x++)
#pragma unroll
        for (int y = 0; y < 4; y++)
            g_kv[obase + (size_t)(td + x) * 64 + te2 + y] = sacc[x][y];
}

__global__ void combine_kernel(const float* __restrict__ tdcy,
                               float* __restrict__ state_out)
{
    int bh = blockIdx.x;
    int h = bh & 31;
    int tid = threadIdx.x;
    float wC = expf(-expf(tdcy[h]) * 128.f);
    float st[16];
#pragma unroll
    for (int q = 0; q < 16; q++) st[q] = 0.f;
    size_t base = (size_t)bh * NC * 4096;
    for (int c = 0; c < NC; c++) {
        size_t off = base + (size_t)c * 4096;
#pragma unroll
        for (int q = 0; q < 16; q++) {
            size_t idx = off + q * 256 + tid;
            g_state[idx] = st[q];
            st[q] = st[q] * wC + g_kv[idx];
        }
    }
#pragma unroll
    for (int q = 0; q < 16; q++)
        state_out[(size_t)bh * 4096 + q * 256 + tid] = st[q];
}

__global__ void bias_kernel(const float* __restrict__ tdcy)
{
    int c = blockIdx.x, bh = blockIdx.y;
    int h = bh & 31, b = bh >> 5;
    int tid = threadIdx.x;
    __shared__ float rs[64][132];
    __shared__ float ss[64][68];
    {
        int lrow = tid >> 1, lc = (tid & 1) * 32;
        size_t rbase = ((size_t)(b*SEQ + c*CK + lrow)) * DM + h * 64 + lc;
#pragma unroll
        for (int m = 0; m < 8; m++) {
            float4 rv = *(const float4*)(g_r + rbase + m * 4);
            int d = lc + m * 4;
            rs[d+0][lrow] = rv.x; rs[d+1][lrow] = rv.y;
            rs[d+2][lrow] = rv.z; rs[d+3][lrow] = rv.w;
        }
        size_t sbase = ((size_t)bh * NC + c) * 4096;
#pragma unroll
        for (int q = 0; q < 16; q++) {
            int idx = q * 256 + tid;
            ss[idx >> 6][idx & 63] = g_state[sbase + idx];
        }
    }
    __syncthreads();
    int ty = tid >> 3, tx = tid & 7;
    float acc[4][8] = {};
#pragma unroll 4
    for (int d = 0; d < 64; d++) {
        float4 a  = *(const float4*)&rs[d][ty * 4];
        float4 b0 = *(const float4*)&ss[d][tx * 8];
        float4 b1 = *(const float4*)&ss[d][tx * 8 + 4];
        float ar[4] = {a.x,a.y,a.z,a.w};
        float br[8] = {b0.x,b0.y,b0.z,b0.w,b1.x,b1.y,b1.z,b1.w};
#pragma unroll
        for (int x = 0; x < 4; x++)
#pragma unroll
            for (int e = 0; e < 8; e++)
                acc[x][e] += ar[x] * br[e];
    }
    float logw = -expf(tdcy[h]);
    size_t obase = ((size_t)(b*SEQ + c*CK)) * DM + h * 64;
#pragma unroll
    for (int x = 0; x < 4; x++) {
        int i = ty * 4 + x;
        float wi = expf(logw * (float)i);
        float* dst = g_att + obase + (size_t)i * DM + tx * 8;
        float4 o0 = *(float4*)dst;
        float4 o1 = *(float4*)(dst + 4);
        o0.x += wi * acc[x][0]; o0.y += wi * acc[x][1];
        o0.z += wi * acc[x][2]; o0.w += wi * acc[x][3];
        o1.x += wi * acc[x][4]; o1.y += wi * acc[x][5];
        o1.z += wi * acc[x][6]; o1.w += wi * acc[x][7];
        *(float4*)dst = o0;
        *(float4*)(dst + 4) = o1;
    }
}

// ---------------- per-head LN (in place on g_att, output rounded to tf32) ----
__global__ void lnx_kernel(const float* __restrict__ sc,
                           const float* __restrict__ bi)
{
    int w = blockIdx.x * 8 + (threadIdx.x >> 5);
    int lid = threadIdx.x & 31;
    int h = w & 31;
    size_t row = (size_t)(w >> 5);
    float* p = g_att + row * DM + h * 64;
    float x0 = p[lid], x1 = p[lid + 32];
    float s = x0 + x1, q = x0 * x0 + x1 * x1;
#pragma unroll
    for (int o = 16; o > 0; o >>= 1) {
        s += __shfl_xor_sync(0xffffffffu, s, o);
        q += __shfl_xor_sync(0xffffffffu, q, o);
    }
    float mu  = s * (1.f / 64.f);
    float inv = rsqrtf(q * (1.f / 64.f) - mu * mu + 1e-5f);
    p[lid]      = roundtf((x0 - mu) * inv * sc[h * 64 + lid]      + bi[h * 64 + lid]);
    p[lid + 32] = roundtf((x1 - mu) * inv * sc[h * 64 + lid + 32] + bi[h * 64 + lid + 32]);
}

// ---------------- launch ----------------
extern "C" void kernel_launch(void* const* d_in, const int* in_sizes, int n_in,
                              void* d_out, int out_size)
{
    const float* inputs = (const float*)d_in[0];
    const float* tmr    = (const float*)d_in[1];
    const float* tmk    = (const float*)d_in[2];
    const float* tmv    = (const float*)d_in[3];
    const float* Wk     = (const float*)d_in[4];
    const float* Wv     = (const float*)d_in[5];
    const float* Wr     = (const float*)d_in[6];
    const float* Wo     = (const float*)d_in[7];
    const float* tdcy   = (const float*)d_in[8];
    const float* tfirst = (const float*)d_in[9];
    const float* ln1s   = (const float*)d_in[10];
    const float* ln1b   = (const float*)d_in[11];
    const float* lnxs   = (const float*)d_in[12];
    const float* lnxb   = (const float*)d_in[13];

    float* out0      = (float*)d_out;
    float* out_xlast = out0 + (size_t)BZ * SEQ * DM;
    float* out_state = out_xlast + (size_t)BZ * DM;

    const int GSMEM = 4 * STG_FLOATS * 4;   // 81920 B
    cudaFuncSetAttribute(tgemm_kernel<0>, cudaFuncAttributeMaxDynamicSharedMemorySize, GSMEM);
    cudaFuncSetAttribute(tgemm_kernel<1>, cudaFuncAttributeMaxDynamicSharedMemorySize, GSMEM);
    cudaFuncSetAttribute(tgemm_kernel<2>, cudaFuncAttributeMaxDynamicSharedMemorySize, GSMEM);
    cudaFuncSetAttribute(tgemm_kernel<3>, cudaFuncAttributeMaxDynamicSharedMemorySize, GSMEM);

    float* wtr; float* wtk; float* wtv; float* wto;
    cudaGetSymbolAddress((void**)&wtr, g_wtr);
    cudaGetSymbolAddress((void**)&wtk, g_wtk);
    cudaGetSymbolAddress((void**)&wtv, g_wtv);
    cudaGetSymbolAddress((void**)&wto, g_wto);

    transpose4_kernel<<<dim3(64, 64, 4), dim3(32, 8)>>>(Wr, wtr, Wk, wtk, Wv, wtv, Wo, wto);
    lnmix_kernel<<<MROWS, 256>>>(inputs, ln1s, ln1b, tmr, tmk, tmv, out_xlast);

    dim3 g(DM / 128, MROWS / 128);
    tgemm_kernel<0><<<g, 128, GSMEM>>>(wtr, nullptr, nullptr);
    tgemm_kernel<1><<<g, 128, GSMEM>>>(wtk, nullptr, nullptr);
    tgemm_kernel<2><<<g, 128, GSMEM>>>(wtv, nullptr, nullptr);
    rkw_kernel<<<dim3(2, 2, BZ * NC * NH), 256>>>(tdcy, tfirst);
    sep_kernel<<<BZ * NC * NH, 256>>>();
    kv_kernel<<<dim3(NC, BZ * NH), 256>>>(tdcy);
    combine_kernel<<<BZ * NH, 256>>>(tdcy, out_state);
    bias_kernel<<<dim3(NC, BZ * NH), 256>>>(tdcy);
    lnx_kernel<<<(MROWS * NH) / 8, 256>>>(lnxs, lnxb);
    tgemm_kernel<3><<<g, 128, GSMEM>>>(wto, inputs, out0);
}

// round 10
// speedup vs baseline: 1.8687x; 1.8687x over previous
#include <cuda_runtime.h>
#include <cuda_fp16.h>
#include <cstdint>

#define SEQ   2048
#define DM    2048
#define NH    32
#define DH    64
#define CK    128
#define NC    16
#define BZ    4
#define MROWS (BZ*SEQ)   // 8192
#define BK    16
#define NKT   (DM/BK)    // 128

// ---------------- scratch (device globals; no allocation) ----------------
__device__ __align__(256) __half g_rxh [BZ*SEQ*DM];
__device__ __align__(256) __half g_kxh [BZ*SEQ*DM];
__device__ __align__(256) __half g_vxh [BZ*SEQ*DM];
__device__ __align__(256) __half g_atth[BZ*SEQ*DM];
__device__ float g_r  [BZ*SEQ*DM];
__device__ float g_k  [BZ*SEQ*DM];
__device__ float g_v  [BZ*SEQ*DM];
__device__ float g_att[BZ*SEQ*DM];
__device__ float g_rkw[(size_t)BZ*NC*NH*CK*CK];
__device__ float g_kv   [BZ*NH*NC*DH*DH];
__device__ float g_state[BZ*NH*NC*DH*DH];
__device__ __align__(256) __half g_wtr[DM*DM];
__device__ __align__(256) __half g_wtk[DM*DM];
__device__ __align__(256) __half g_wtv[DM*DM];
__device__ __align__(256) __half g_wto[DM*DM];

// ---------------- small PTX helpers ----------------
__device__ __forceinline__ uint32_t smem_u32(const void* p)
{
    uint32_t a;
    asm("{ .reg .u64 t; cvta.to.shared.u64 t, %1; cvt.u32.u64 %0, t; }" : "=r"(a) : "l"(p));
    return a;
}
template<int N> __device__ __forceinline__ void cp_wait()
{
    asm volatile("cp.async.wait_group %0;" :: "n"(N) : "memory");
}
__device__ __forceinline__ void cp16(uint32_t dst, const void* src)
{
    asm volatile("cp.async.cg.shared.global [%0], [%1], 16;" :: "r"(dst), "l"(src));
}
__device__ __forceinline__ void cp_commit()
{
    asm volatile("cp.async.commit_group;" ::: "memory");
}
__device__ __forceinline__ void mma_f16(float* c, const unsigned* a, const unsigned* b)
{
    asm volatile(
        "mma.sync.aligned.m16n8k16.row.col.f32.f16.f16.f32 "
        "{%0,%1,%2,%3}, {%4,%5,%6,%7}, {%8,%9}, {%0,%1,%2,%3};"
        : "+f"(c[0]), "+f"(c[1]), "+f"(c[2]), "+f"(c[3])
        : "r"(a[0]), "r"(a[1]), "r"(a[2]), "r"(a[3]),
          "r"(b[0]), "r"(b[1]));
}
__device__ __forceinline__ void ldsm4(unsigned* r, uint32_t addr)
{
    asm volatile("ldmatrix.sync.aligned.m8n8.x4.shared.b16 {%0,%1,%2,%3}, [%4];"
        : "=r"(r[0]), "=r"(r[1]), "=r"(r[2]), "=r"(r[3]) : "r"(addr));
}

// ---------------- fused LN + token-shift mixing (fp16 outputs) ------------
__global__ void lnmix_kernel(const float* __restrict__ x,
                             const float* __restrict__ sc,
                             const float* __restrict__ bi,
                             const float* __restrict__ tmr,
                             const float* __restrict__ tmk,
                             const float* __restrict__ tmv,
                             float* __restrict__ xlast)
{
    int row = blockIdx.x;
    int t   = row & (SEQ - 1);
    const float* xr = x + (size_t)row * DM;
    float cur[8], prv[8];
    float s0 = 0.f, q0 = 0.f, s1 = 0.f, q1 = 0.f;
#pragma unroll
    for (int i = 0; i < 8; i++) {
        int c = threadIdx.x + i * 256;
        float v = xr[c];
        cur[i] = v; s0 += v; q0 += v * v;
        float u = t ? xr[c - DM] : 0.f;
        prv[i] = u; s1 += u; q1 += u * u;
    }
#pragma unroll
    for (int o = 16; o > 0; o >>= 1) {
        s0 += __shfl_xor_sync(0xffffffffu, s0, o);
        q0 += __shfl_xor_sync(0xffffffffu, q0, o);
        s1 += __shfl_xor_sync(0xffffffffu, s1, o);
        q1 += __shfl_xor_sync(0xffffffffu, q1, o);
    }
    __shared__ float rs0[8], rq0[8], rs1[8], rq1[8];
    int w = threadIdx.x >> 5;
    if ((threadIdx.x & 31) == 0) { rs0[w] = s0; rq0[w] = q0; rs1[w] = s1; rq1[w] = q1; }
    __syncthreads();
    s0 = 0.f; q0 = 0.f; s1 = 0.f; q1 = 0.f;
#pragma unroll
    for (int i = 0; i < 8; i++) { s0 += rs0[i]; q0 += rq0[i]; s1 += rs1[i]; q1 += rq1[i]; }
    float mu0  = s0 * (1.f / DM);
    float inv0 = rsqrtf(q0 * (1.f / DM) - mu0 * mu0 + 1e-5f);
    float mu1  = s1 * (1.f / DM);
    float inv1 = rsqrtf(q1 * (1.f / DM) - mu1 * mu1 + 1e-5f);
    bool last = (t == SEQ - 1);
#pragma unroll
    for (int i = 0; i < 8; i++) {
        int c = threadIdx.x + i * 256;
        float yc = (cur[i] - mu0) * inv0 * sc[c] + bi[c];
        float yp = t ? (prv[i] - mu1) * inv1 * sc[c] + bi[c] : 0.f;
        size_t off = (size_t)row * DM + c;
        float mr = tmr[c], mk = tmk[c], mv = tmv[c];
        g_rxh[off] = __float2half(yc * mr + (1.f - mr) * yp);
        g_kxh[off] = __float2half(yc * mk + (1.f - mk) * yp);
        g_vxh[off] = __float2half(yc * mv + (1.f - mv) * yp);
        if (last) xlast[(row >> 11) * DM + c] = yc;
    }
}

// ---------------- 4 weight transposes in one launch (fp16 outputs) --------
__global__ void transpose4_kernel(const float* __restrict__ s0, __half* __restrict__ d0,
                                  const float* __restrict__ s1, __half* __restrict__ d1,
                                  const float* __restrict__ s2, __half* __restrict__ d2,
                                  const float* __restrict__ s3, __half* __restrict__ d3)
{
    const float* src; __half* dst;
    switch (blockIdx.z) {
        case 0:  src = s0; dst = d0; break;
        case 1:  src = s1; dst = d1; break;
        case 2:  src = s2; dst = d2; break;
        default: src = s3; dst = d3; break;
    }
    __shared__ float t[32][33];
    int bx = blockIdx.x * 32, by = blockIdx.y * 32;
#pragma unroll
    for (int i = 0; i < 4; i++)
        t[threadIdx.y + i * 8][threadIdx.x] =
            src[(size_t)(by + threadIdx.y + i * 8) * DM + bx + threadIdx.x];
    __syncthreads();
#pragma unroll
    for (int i = 0; i < 4; i++)
        dst[(size_t)(bx + threadIdx.y + i * 8) * DM + by + threadIdx.x] =
            __float2half(t[threadIdx.x][threadIdx.y + i * 8]);
}

// ---------------- fp16 mma.sync GEMM, cp.async 4-stage, ldmatrix ----------
// C[8192x2048] = A @ Bt^T (A [m][k] fp16, Bt [n][k] fp16), fp32 accum/output.
// 256 threads, block tile 128x128x16, 8 warps as 2(m) x 4(n), warp tile 64x32.
#define HSTRIDE 24                        // halves per smem row (16 data + 8 pad)
#define STG_BYTES (2 * 128 * HSTRIDE * 2) // A tile + B tile per stage = 12288 B

template<int MODE>
__global__ void __launch_bounds__(256, 2) tgemm_kernel(const __half* __restrict__ Bt,
                                                       const float* __restrict__ Add,
                                                       float* __restrict__ Out)
{
    const __half* A;
    float* C;
    if constexpr (MODE == 0) { A = g_rxh; C = g_r; }
    else if constexpr (MODE == 1) { A = g_kxh; C = g_k; }
    else if constexpr (MODE == 2) { A = g_vxh; C = g_v; }
    else { A = g_atth; C = Out; }

    extern __shared__ char smem[];
    uint32_t sb = smem_u32(smem);
    int tid = threadIdx.x, lane = tid & 31, warp = tid >> 5;
    int r0 = lane >> 2, c0 = lane & 3;
    int wm = (warp >> 2) * 64, wn = (warp & 3) * 32;
    int bm = blockIdx.y * 128, bn = blockIdx.x * 128;

    const __half* Ag = A  + (size_t)bm * DM;
    const __half* Bg = Bt + (size_t)bn * DM;

    // ldmatrix per-lane addresses (byte offsets into tile)
    int lane7 = lane & 7;
    uint32_t a_off = (uint32_t)(((wm + ((lane >> 3) & 1) * 8 + lane7) * HSTRIDE
                                + ((lane >> 4) & 1) * 8) * 2);
    uint32_t b_off = (uint32_t)(((wn + ((lane >> 4) & 1) * 8 + lane7) * HSTRIDE
                                + ((lane >> 3) & 1) * 8) * 2);

    // copy: thread -> one 16B chunk of A row + one of B row
    int cm = tid >> 1, cq = (tid & 1) * 8;    // row, half-offset
    auto copy_stage = [&](int buf, int kt) {
        uint32_t sA = sb + buf * STG_BYTES;
        uint32_t sB = sA + 128 * HSTRIDE * 2;
        uint32_t off = cm * (HSTRIDE * 2) + cq * 2;
        cp16(sA + off, Ag + kt * BK + (size_t)cm * DM + cq);
        cp16(sB + off, Bg + kt * BK + (size_t)cm * DM + cq);
        cp_commit();
    };

    float acc[4][4][4];
#pragma unroll
    for (int i = 0; i < 4; i++)
#pragma unroll
        for (int j = 0; j < 4; j++)
#pragma unroll
            for (int e = 0; e < 4; e++) acc[i][j][e] = 0.f;

    copy_stage(0, 0);
    copy_stage(1, 1);
    copy_stage(2, 2);
    cp_wait<2>();
    __syncthreads();

    for (int kt = 0; kt < NKT; kt++) {
        int buf = kt & 3;
        uint32_t sA = sb + buf * STG_BYTES;
        uint32_t sB = sA + 128 * HSTRIDE * 2;
        unsigned af[4][4], bf[8];
#pragma unroll
        for (int i = 0; i < 4; i++)
            ldsm4(af[i], sA + a_off + i * (16 * HSTRIDE * 2));
        ldsm4(&bf[0], sB + b_off);
        ldsm4(&bf[4], sB + b_off + 16 * HSTRIDE * 2);
#pragma unroll
        for (int i = 0; i < 4; i++)
#pragma unroll
            for (int j = 0; j < 4; j++)
                mma_f16(acc[i][j], af[i], &bf[j * 2]);
        // one commit-group per iteration (empty in tail) keeps wait<2>'s
        // "next tile resident" invariant through the last iterations
        if (kt + 3 < NKT) copy_stage((kt + 3) & 3, kt + 3);
        else              cp_commit();
        cp_wait<2>();
        __syncthreads();
    }

#pragma unroll
    for (int i = 0; i < 4; i++) {
        int row = bm + wm + i * 16 + r0;
#pragma unroll
        for (int j = 0; j < 4; j++) {
            int col = bn + wn + j * 8 + c0 * 2;
            size_t o0 = (size_t)row * DM + col;
            size_t o1 = (size_t)(row + 8) * DM + col;
            float2 v0 = make_float2(acc[i][j][0], acc[i][j][1]);
            float2 v1 = make_float2(acc[i][j][2], acc[i][j][3]);
            if constexpr (MODE == 3) {
                float2 a0 = *(const float2*)(Add + o0);
                float2 a1 = *(const float2*)(Add + o1);
                v0.x += a0.x; v0.y += a0.y;
                v1.x += a1.x; v1.y += a1.y;
            }
            *(float2*)(C + o0) = v0;
            *(float2*)(C + o1) = v1;
        }
    }
}

// ---------------- rkw = (r @ k^T) * mask, per (b,chunk,head), 64x64 tiles --
__global__ void rkw_kernel(const float* __restrict__ tdcy,
                           const float* __restrict__ tfirst)
{
    int jt = blockIdx.x, it = blockIdx.y, bch = blockIdx.z;
    int h = bch & 31;
    int chunk = (bch >> 5) & 15;
    int b = bch >> 9;
    __shared__ float rs[64][68];
    __shared__ float ks[64][68];
    int tid = threadIdx.x;
    int lrow = tid >> 2;
    int lc4  = (tid & 3) * 16;
    size_t rbase = ((size_t)(b*SEQ + chunk*CK + it*64 + lrow)) * DM + h*64 + lc4;
    size_t kbase = ((size_t)(b*SEQ + chunk*CK + jt*64 + lrow)) * DM + h*64 + lc4;
#pragma unroll
    for (int m = 0; m < 4; m++) {
        float4 rv = *(const float4*)(g_r + rbase + m * 4);
        float4 kv = *(const float4*)(g_k + kbase + m * 4);
        int d = lc4 + m * 4;
        rs[d+0][lrow] = rv.x; rs[d+1][lrow] = rv.y; rs[d+2][lrow] = rv.z; rs[d+3][lrow] = rv.w;
        ks[d+0][lrow] = kv.x; ks[d+1][lrow] = kv.y; ks[d+2][lrow] = kv.z; ks[d+3][lrow] = kv.w;
    }
    __syncthreads();
    int tx = tid & 15, ty = tid >> 4;
    float acc[4][4] = {};
#pragma unroll 8
    for (int d = 0; d < 64; d++) {
        float4 a = *(const float4*)&rs[d][ty * 4];
        float4 bq = *(const float4*)&ks[d][tx * 4];
        float ar[4] = {a.x,a.y,a.z,a.w};
        float br[4] = {bq.x,bq.y,bq.z,bq.w};
#pragma unroll
        for (int x = 0; x < 4; x++)
#pragma unroll
            for (int y = 0; y < 4; y++)
                acc[x][y] += ar[x] * br[y];
    }
    float logw = -expf(tdcy[h]);
    float u    =  expf(tfirst[h]);
#pragma unroll
    for (int x = 0; x < 4; x++)
#pragma unroll
        for (int y = 0; y < 4; y++) {
            int i = it * 64 + ty * 4 + x;
            int j = jt * 64 + tx * 4 + y;
            float m;
            if (i > j)      m = expf(logw * (float)(i - j - 1));
            else if (i == j) m = u;
            else             m = 0.f;
            g_rkw[((size_t)bch * CK + i) * CK + j] = acc[x][y] * m;
        }
}

// ---------------- sep = rkw @ v, per (b,chunk,head) ----------------
__global__ void sep_kernel()
{
    int bch = blockIdx.x;
    int h = bch & 31;
    int chunk = (bch >> 5) & 15;
    int b = bch >> 9;
    int tid = threadIdx.x;
    __shared__ float vs[128][64];
    __shared__ float rk[16][132];
    {
        int row = tid >> 1, e0 = (tid & 1) * 32;
        size_t base = ((size_t)(b*SEQ + chunk*CK + row)) * DM + h*64 + e0;
#pragma unroll
        for (int m = 0; m < 8; m++)
            *(float4*)&vs[row][e0 + m * 4] = *(const float4*)(g_v + base + m * 4);
    }
    int ty = tid >> 3, tx = tid & 7;
    float acc[4][8] = {};
    int rrow = tid >> 1, jc = (tid & 1) * 8;
    for (int s = 0; s < 8; s++) {
        const float* src = g_rkw + ((size_t)bch * CK + rrow) * CK + s * 16 + jc;
        float4 r0 = *(const float4*)src;
        float4 r1 = *(const float4*)(src + 4);
        __syncthreads();
        rk[jc+0][rrow] = r0.x; rk[jc+1][rrow] = r0.y; rk[jc+2][rrow] = r0.z; rk[jc+3][rrow] = r0.w;
        rk[jc+4][rrow] = r1.x; rk[jc+5][rrow] = r1.y; rk[jc+6][rrow] = r1.z; rk[jc+7][rrow] = r1.w;
        __syncthreads();
#pragma unroll
        for (int jj = 0; jj < 16; jj++) {
            float4 a  = *(const float4*)&rk[jj][ty * 4];
            float4 b0 = *(const float4*)&vs[s * 16 + jj][tx * 8];
            float4 b1 = *(const float4*)&vs[s * 16 + jj][tx * 8 + 4];
            float ar[4] = {a.x,a.y,a.z,a.w};
            float br[8] = {b0.x,b0.y,b0.z,b0.w,b1.x,b1.y,b1.z,b1.w};
#pragma unroll
            for (int x = 0; x < 4; x++)
#pragma unroll
                for (int e = 0; e < 8; e++)
                    acc[x][e] += ar[x] * br[e];
        }
    }
    size_t obase = ((size_t)(b*SEQ + chunk*CK)) * DM + h*64;
#pragma unroll
    for (int x = 0; x < 4; x++) {
        size_t ro = obase + (size_t)(ty * 4 + x) * DM + tx * 8;
        float4 o0, o1;
        o0.x = acc[x][0]; o0.y = acc[x][1]; o0.z = acc[x][2]; o0.w = acc[x][3];
        o1.x = acc[x][4]; o1.y = acc[x][5]; o1.z = acc[x][6]; o1.w = acc[x][7];
        *(float4*)(g_att + ro)     = o0;
        *(float4*)(g_att + ro + 4) = o1;
    }
}

// ---------------- scan decomposition ----------------
__global__ void kv_kernel(const float* __restrict__ tdcy)
{
    int c = blockIdx.x, bh = blockIdx.y;
    int h = bh & 31, b = bh >> 5;
    int tid = threadIdx.x;
    __shared__ float bufA[32][68];
    __shared__ float bufB[32][68];
    float logw = -expf(tdcy[h]);
    int lrow = tid >> 3, lcol = (tid & 7) * 8;
    int td = (tid >> 4) * 4, te2 = (tid & 15) * 4;
    size_t base = ((size_t)(b*SEQ + c*CK)) * DM + h * 64;
    float sacc[4][4] = {};
    for (int s4 = 0; s4 < 4; s4++) {
        int j = s4 * 32 + lrow;
        float wk = expf(logw * (float)(127 - j));
        const float* ksrc = g_k + base + (size_t)j * DM + lcol;
        const float* vsrc = g_v + base + (size_t)j * DM + lcol;
        float4 k0 = *(const float4*)ksrc;
        float4 k1 = *(const float4*)(ksrc + 4);
        float4 w0 = *(const float4*)vsrc;
        float4 w1 = *(const float4*)(vsrc + 4);
        k0.x *= wk; k0.y *= wk; k0.z *= wk; k0.w *= wk;
        k1.x *= wk; k1.y *= wk; k1.z *= wk; k1.w *= wk;
        *(float4*)&bufA[lrow][lcol]     = k0;
        *(float4*)&bufA[lrow][lcol + 4] = k1;
        *(float4*)&bufB[lrow][lcol]     = w0;
        *(float4*)&bufB[lrow][lcol + 4] = w1;
        __syncthreads();
#pragma unroll 4
        for (int jj = 0; jj < 32; jj++) {
            float4 ka = *(const float4*)&bufA[jj][td];
            float4 vb = *(const float4*)&bufB[jj][te2];
            float ar[4] = {ka.x,ka.y,ka.z,ka.w};
            float br[4] = {vb.x,vb.y,vb.z,vb.w};
#pragma unroll
            for (int x = 0; x < 4; x++)
#pragma unroll
                for (int y = 0; y < 4; y++)
                    sacc[x][y] += ar[x] * br[y];
        }
        __syncthreads();
    }
    size_t obase = ((size_t)bh * NC + c) * 4096;
#pragma unroll
    for (int x = 0; x < 4; x++)
#pragma unroll
        for (int y = 0; y < 4; y++)
            g_kv[obase + (size_t)(td + x) * 64 + te2 + y] = sacc[x][y];
}

__global__ void combine_kernel(const float* __restrict__ tdcy,
                               float* __restrict__ state_out)
{
    int bh = blockIdx.x;
    int h = bh & 31;
    int tid = threadIdx.x;
    float wC = expf(-expf(tdcy[h]) * 128.f);
    float st[16];
#pragma unroll
    for (int q = 0; q < 16; q++) st[q] = 0.f;
    size_t base = (size_t)bh * NC * 4096;
    for (int c = 0; c < NC; c++) {
        size_t off = base + (size_t)c * 4096;
#pragma unroll
        for (int q = 0; q < 16; q++) {
            size_t idx = off + q * 256 + tid;
            g_state[idx] = st[q];
            st[q] = st[q] * wC + g_kv[idx];
        }
    }
#pragma unroll
    for (int q = 0; q < 16; q++)
        state_out[(size_t)bh * 4096 + q * 256 + tid] = st[q];
}

__global__ void bias_kernel(const float* __restrict__ tdcy)
{
    int c = blockIdx.x, bh = blockIdx.y;
    int h = bh & 31, b = bh >> 5;
    int tid = threadIdx.x;
    __shared__ float rs[64][132];
    __shared__ float ss[64][68];
    {
        int lrow = tid >> 1, lc = (tid & 1) * 32;
        size_t rbase = ((size_t)(b*SEQ + c*CK + lrow)) * DM + h * 64 + lc;
#pragma unroll
        for (int m = 0; m < 8; m++) {
            float4 rv = *(const float4*)(g_r + rbase + m * 4);
            int d = lc + m * 4;
            rs[d+0][lrow] = rv.x; rs[d+1][lrow] = rv.y;
            rs[d+2][lrow] = rv.z; rs[d+3][lrow] = rv.w;
        }
        size_t sbase = ((size_t)bh * NC + c) * 4096;
#pragma unroll
        for (int q = 0; q < 16; q++) {
            int idx = q * 256 + tid;
            ss[idx >> 6][idx & 63] = g_state[sbase + idx];
        }
    }
    __syncthreads();
    int ty = tid >> 3, tx = tid & 7;
    float acc[4][8] = {};
#pragma unroll 4
    for (int d = 0; d < 64; d++) {
        float4 a  = *(const float4*)&rs[d][ty * 4];
        float4 b0 = *(const float4*)&ss[d][tx * 8];
        float4 b1 = *(const float4*)&ss[d][tx * 8 + 4];
        float ar[4] = {a.x,a.y,a.z,a.w};
        float br[8] = {b0.x,b0.y,b0.z,b0.w,b1.x,b1.y,b1.z,b1.w};
#pragma unroll
        for (int x = 0; x < 4; x++)
#pragma unroll
            for (int e = 0; e < 8; e++)
                acc[x][e] += ar[x] * br[e];
    }
    float logw = -expf(tdcy[h]);
    size_t obase = ((size_t)(b*SEQ + c*CK)) * DM + h * 64;
#pragma unroll
    for (int x = 0; x < 4; x++) {
        int i = ty * 4 + x;
        float wi = expf(logw * (float)i);
        float* dst = g_att + obase + (size_t)i * DM + tx * 8;
        float4 o0 = *(float4*)dst;
        float4 o1 = *(float4*)(dst + 4);
        o0.x += wi * acc[x][0]; o0.y += wi * acc[x][1];
        o0.z += wi * acc[x][2]; o0.w += wi * acc[x][3];
        o1.x += wi * acc[x][4]; o1.y += wi * acc[x][5];
        o1.z += wi * acc[x][6]; o1.w += wi * acc[x][7];
        *(float4*)dst = o0;
        *(float4*)(dst + 4) = o1;
    }
}

// ---------------- per-head LN: g_att (fp32) -> g_atth (fp16) ----------------
__global__ void lnx_kernel(const float* __restrict__ sc,
                           const float* __restrict__ bi)
{
    int w = blockIdx.x * 8 + (threadIdx.x >> 5);
    int lid = threadIdx.x & 31;
    int h = w & 31;
    size_t row = (size_t)(w >> 5);
    const float* p = g_att + row * DM + h * 64;
    __half* po = g_atth + row * DM + h * 64;
    float x0 = p[lid], x1 = p[lid + 32];
    float s = x0 + x1, q = x0 * x0 + x1 * x1;
#pragma unroll
    for (int o = 16; o > 0; o >>= 1) {
        s += __shfl_xor_sync(0xffffffffu, s, o);
        q += __shfl_xor_sync(0xffffffffu, q, o);
    }
    float mu  = s * (1.f / 64.f);
    float inv = rsqrtf(q * (1.f / 64.f) - mu * mu + 1e-5f);
    po[lid]      = __float2half((x0 - mu) * inv * sc[h * 64 + lid]      + bi[h * 64 + lid]);
    po[lid + 32] = __float2half((x1 - mu) * inv * sc[h * 64 + lid + 32] + bi[h * 64 + lid + 32]);
}

// ---------------- launch ----------------
extern "C" void kernel_launch(void* const* d_in, const int* in_sizes, int n_in,
                              void* d_out, int out_size)
{
    const float* inputs = (const float*)d_in[0];
    const float* tmr    = (const float*)d_in[1];
    const float* tmk    = (const float*)d_in[2];
    const float* tmv    = (const float*)d_in[3];
    const float* Wk     = (const float*)d_in[4];
    const float* Wv     = (const float*)d_in[5];
    const float* Wr     = (const float*)d_in[6];
    const float* Wo     = (const float*)d_in[7];
    const float* tdcy   = (const float*)d_in[8];
    const float* tfirst = (const float*)d_in[9];
    const float* ln1s   = (const float*)d_in[10];
    const float* ln1b   = (const float*)d_in[11];
    const float* lnxs   = (const float*)d_in[12];
    const float* lnxb   = (const float*)d_in[13];

    float* out0      = (float*)d_out;
    float* out_xlast = out0 + (size_t)BZ * SEQ * DM;
    float* out_state = out_xlast + (size_t)BZ * DM;

    const int GSMEM = 4 * STG_BYTES;   // 49152 B
    cudaFuncSetAttribute(tgemm_kernel<0>, cudaFuncAttributeMaxDynamicSharedMemorySize, GSMEM);
    cudaFuncSetAttribute(tgemm_kernel<1>, cudaFuncAttributeMaxDynamicSharedMemorySize, GSMEM);
    cudaFuncSetAttribute(tgemm_kernel<2>, cudaFuncAttributeMaxDynamicSharedMemorySize, GSMEM);
    cudaFuncSetAttribute(tgemm_kernel<3>, cudaFuncAttributeMaxDynamicSharedMemorySize, GSMEM);

    __half* wtr; __half* wtk; __half* wtv; __half* wto;
    cudaGetSymbolAddress((void**)&wtr, g_wtr);
    cudaGetSymbolAddress((void**)&wtk, g_wtk);
    cudaGetSymbolAddress((void**)&wtv, g_wtv);
    cudaGetSymbolAddress((void**)&wto, g_wto);

    transpose4_kernel<<<dim3(64, 64, 4), dim3(32, 8)>>>(Wr, wtr, Wk, wtk, Wv, wtv, Wo, wto);
    lnmix_kernel<<<MROWS, 256>>>(inputs, ln1s, ln1b, tmr, tmk, tmv, out_xlast);

    dim3 g(DM / 128, MROWS / 128);
    tgemm_kernel<0><<<g, 256, GSMEM>>>(wtr, nullptr, nullptr);
    tgemm_kernel<1><<<g, 256, GSMEM>>>(wtk, nullptr, nullptr);
    tgemm_kernel<2><<<g, 256, GSMEM>>>(wtv, nullptr, nullptr);
    rkw_kernel<<<dim3(2, 2, BZ * NC * NH), 256>>>(tdcy, tfirst);
    sep_kernel<<<BZ * NC * NH, 256>>>();
    kv_kernel<<<dim3(NC, BZ * NH), 256>>>(tdcy);
    combine_kernel<<<BZ * NH, 256>>>(tdcy, out_state);
    bias_kernel<<<dim3(NC, BZ * NH), 256>>>(tdcy);
    lnx_kernel<<<(MROWS * NH) / 8, 256>>>(lnxs, lnxb);
    tgemm_kernel<3><<<g, 256, GSMEM>>>(wto, inputs, out0);
}

// round 11
// speedup vs baseline: 2.2499x; 1.2040x over previous
#include <cuda_runtime.h>
#include <cuda_fp16.h>
#include <cstdint>

#define SEQ   2048
#define DM    2048
#define NH    32
#define DH    64
#define CK    128
#define NC    16
#define BZ    4
#define MROWS (BZ*SEQ)   // 8192
#define BK    16
#define NKT   (DM/BK)    // 128

// ---------------- scratch (device globals; no allocation) ----------------
__device__ __align__(256) __half g_rxh [BZ*SEQ*DM];
__device__ __align__(256) __half g_kxh [BZ*SEQ*DM];
__device__ __align__(256) __half g_vxh [BZ*SEQ*DM];
__device__ __align__(256) __half g_atth[BZ*SEQ*DM];
__device__ float g_r  [BZ*SEQ*DM];
__device__ float g_k  [BZ*SEQ*DM];
__device__ float g_v  [BZ*SEQ*DM];
__device__ float g_att[BZ*SEQ*DM];
__device__ float g_kv   [BZ*NH*NC*DH*DH];
__device__ float g_state[BZ*NH*NC*DH*DH];
__device__ __align__(256) __half g_wtr[DM*DM];
__device__ __align__(256) __half g_wtk[DM*DM];
__device__ __align__(256) __half g_wtv[DM*DM];
__device__ __align__(256) __half g_wto[DM*DM];

// ---------------- small PTX helpers ----------------
__device__ __forceinline__ uint32_t smem_u32(const void* p)
{
    uint32_t a;
    asm("{ .reg .u64 t; cvta.to.shared.u64 t, %1; cvt.u32.u64 %0, t; }" : "=r"(a) : "l"(p));
    return a;
}
template<int N> __device__ __forceinline__ void cp_wait()
{
    asm volatile("cp.async.wait_group %0;" :: "n"(N) : "memory");
}
__device__ __forceinline__ void cp16(uint32_t dst, const void* src)
{
    asm volatile("cp.async.cg.shared.global [%0], [%1], 16;" :: "r"(dst), "l"(src));
}
__device__ __forceinline__ void cp_commit()
{
    asm volatile("cp.async.commit_group;" ::: "memory");
}
__device__ __forceinline__ void mma_f16(float* c, const unsigned* a, const unsigned* b)
{
    asm volatile(
        "mma.sync.aligned.m16n8k16.row.col.f32.f16.f16.f32 "
        "{%0,%1,%2,%3}, {%4,%5,%6,%7}, {%8,%9}, {%0,%1,%2,%3};"
        : "+f"(c[0]), "+f"(c[1]), "+f"(c[2]), "+f"(c[3])
        : "r"(a[0]), "r"(a[1]), "r"(a[2]), "r"(a[3]),
          "r"(b[0]), "r"(b[1]));
}
__device__ __forceinline__ void ldsm4(unsigned* r, uint32_t addr)
{
    asm volatile("ldmatrix.sync.aligned.m8n8.x4.shared.b16 {%0,%1,%2,%3}, [%4];"
        : "=r"(r[0]), "=r"(r[1]), "=r"(r[2]), "=r"(r[3]) : "r"(addr));
}
__device__ __forceinline__ void ldsm4t(unsigned* r, uint32_t addr)
{
    asm volatile("ldmatrix.sync.aligned.m8n8.x4.trans.shared.b16 {%0,%1,%2,%3}, [%4];"
        : "=r"(r[0]), "=r"(r[1]), "=r"(r[2]), "=r"(r[3]) : "r"(addr));
}

// ---------------- fused LN + token-shift mixing (fp16 outputs) ------------
__global__ void lnmix_kernel(const float* __restrict__ x,
                             const float* __restrict__ sc,
                             const float* __restrict__ bi,
                             const float* __restrict__ tmr,
                             const float* __restrict__ tmk,
                             const float* __restrict__ tmv,
                             float* __restrict__ xlast)
{
    int row = blockIdx.x;
    int t   = row & (SEQ - 1);
    const float* xr = x + (size_t)row * DM;
    float cur[8], prv[8];
    float s0 = 0.f, q0 = 0.f, s1 = 0.f, q1 = 0.f;
#pragma unroll
    for (int i = 0; i < 8; i++) {
        int c = threadIdx.x + i * 256;
        float v = xr[c];
        cur[i] = v; s0 += v; q0 += v * v;
        float u = t ? xr[c - DM] : 0.f;
        prv[i] = u; s1 += u; q1 += u * u;
    }
#pragma unroll
    for (int o = 16; o > 0; o >>= 1) {
        s0 += __shfl_xor_sync(0xffffffffu, s0, o);
        q0 += __shfl_xor_sync(0xffffffffu, q0, o);
        s1 += __shfl_xor_sync(0xffffffffu, s1, o);
        q1 += __shfl_xor_sync(0xffffffffu, q1, o);
    }
    __shared__ float rs0[8], rq0[8], rs1[8], rq1[8];
    int w = threadIdx.x >> 5;
    if ((threadIdx.x & 31) == 0) { rs0[w] = s0; rq0[w] = q0; rs1[w] = s1; rq1[w] = q1; }
    __syncthreads();
    s0 = 0.f; q0 = 0.f; s1 = 0.f; q1 = 0.f;
#pragma unroll
    for (int i = 0; i < 8; i++) { s0 += rs0[i]; q0 += rq0[i]; s1 += rs1[i]; q1 += rq1[i]; }
    float mu0  = s0 * (1.f / DM);
    float inv0 = rsqrtf(q0 * (1.f / DM) - mu0 * mu0 + 1e-5f);
    float mu1  = s1 * (1.f / DM);
    float inv1 = rsqrtf(q1 * (1.f / DM) - mu1 * mu1 + 1e-5f);
    bool last = (t == SEQ - 1);
#pragma unroll
    for (int i = 0; i < 8; i++) {
        int c = threadIdx.x + i * 256;
        float yc = (cur[i] - mu0) * inv0 * sc[c] + bi[c];
        float yp = t ? (prv[i] - mu1) * inv1 * sc[c] + bi[c] : 0.f;
        size_t off = (size_t)row * DM + c;
        float mr = tmr[c], mk = tmk[c], mv = tmv[c];
        g_rxh[off] = __float2half(yc * mr + (1.f - mr) * yp);
        g_kxh[off] = __float2half(yc * mk + (1.f - mk) * yp);
        g_vxh[off] = __float2half(yc * mv + (1.f - mv) * yp);
        if (last) xlast[(row >> 11) * DM + c] = yc;
    }
}

// ---------------- 4 weight transposes in one launch (fp16 outputs) --------
__global__ void transpose4_kernel(const float* __restrict__ s0, __half* __restrict__ d0,
                                  const float* __restrict__ s1, __half* __restrict__ d1,
                                  const float* __restrict__ s2, __half* __restrict__ d2,
                                  const float* __restrict__ s3, __half* __restrict__ d3)
{
    const float* src; __half* dst;
    switch (blockIdx.z) {
        case 0:  src = s0; dst = d0; break;
        case 1:  src = s1; dst = d1; break;
        case 2:  src = s2; dst = d2; break;
        default: src = s3; dst = d3; break;
    }
    __shared__ float t[32][33];
    int bx = blockIdx.x * 32, by = blockIdx.y * 32;
#pragma unroll
    for (int i = 0; i < 4; i++)
        t[threadIdx.y + i * 8][threadIdx.x] =
            src[(size_t)(by + threadIdx.y + i * 8) * DM + bx + threadIdx.x];
    __syncthreads();
#pragma unroll
    for (int i = 0; i < 4; i++)
        dst[(size_t)(bx + threadIdx.y + i * 8) * DM + by + threadIdx.x] =
            __float2half(t[threadIdx.x][threadIdx.y + i * 8]);
}

// ---------------- fp16 mma.sync GEMM, cp.async 4-stage, ldmatrix ----------
#define HSTRIDE 24                        // halves per smem row (16 data + 8 pad)
#define STG_BYTES (2 * 128 * HSTRIDE * 2) // A tile + B tile per stage = 12288 B

template<int MODE>
__global__ void __launch_bounds__(256, 2) tgemm_kernel(const __half* __restrict__ Bt,
                                                       const float* __restrict__ Add,
                                                       float* __restrict__ Out)
{
    const __half* A;
    float* C;
    if constexpr (MODE == 0) { A = g_rxh; C = g_r; }
    else if constexpr (MODE == 1) { A = g_kxh; C = g_k; }
    else if constexpr (MODE == 2) { A = g_vxh; C = g_v; }
    else { A = g_atth; C = Out; }

    extern __shared__ char smem[];
    uint32_t sb = smem_u32(smem);
    int tid = threadIdx.x, lane = tid & 31, warp = tid >> 5;
    int r0 = lane >> 2, c0 = lane & 3;
    int wm = (warp >> 2) * 64, wn = (warp & 3) * 32;
    int bm = blockIdx.y * 128, bn = blockIdx.x * 128;

    const __half* Ag = A  + (size_t)bm * DM;
    const __half* Bg = Bt + (size_t)bn * DM;

    int lane7 = lane & 7;
    uint32_t a_off = (uint32_t)(((wm + ((lane >> 3) & 1) * 8 + lane7) * HSTRIDE
                                + ((lane >> 4) & 1) * 8) * 2);
    uint32_t b_off = (uint32_t)(((wn + ((lane >> 4) & 1) * 8 + lane7) * HSTRIDE
                                + ((lane >> 3) & 1) * 8) * 2);

    int cm = tid >> 1, cq = (tid & 1) * 8;
    auto copy_stage = [&](int buf, int kt) {
        uint32_t sA = sb + buf * STG_BYTES;
        uint32_t sB = sA + 128 * HSTRIDE * 2;
        uint32_t off = cm * (HSTRIDE * 2) + cq * 2;
        cp16(sA + off, Ag + kt * BK + (size_t)cm * DM + cq);
        cp16(sB + off, Bg + kt * BK + (size_t)cm * DM + cq);
        cp_commit();
    };

    float acc[4][4][4];
#pragma unroll
    for (int i = 0; i < 4; i++)
#pragma unroll
        for (int j = 0; j < 4; j++)
#pragma unroll
            for (int e = 0; e < 4; e++) acc[i][j][e] = 0.f;

    copy_stage(0, 0);
    copy_stage(1, 1);
    copy_stage(2, 2);
    cp_wait<2>();
    __syncthreads();

    for (int kt = 0; kt < NKT; kt++) {
        int buf = kt & 3;
        uint32_t sA = sb + buf * STG_BYTES;
        uint32_t sB = sA + 128 * HSTRIDE * 2;
        unsigned af[4][4], bf[8];
#pragma unroll
        for (int i = 0; i < 4; i++)
            ldsm4(af[i], sA + a_off + i * (16 * HSTRIDE * 2));
        ldsm4(&bf[0], sB + b_off);
        ldsm4(&bf[4], sB + b_off + 16 * HSTRIDE * 2);
#pragma unroll
        for (int i = 0; i < 4; i++)
#pragma unroll
            for (int j = 0; j < 4; j++)
                mma_f16(acc[i][j], af[i], &bf[j * 2]);
        if (kt + 3 < NKT) copy_stage((kt + 3) & 3, kt + 3);
        else              cp_commit();
        cp_wait<2>();
        __syncthreads();
    }

#pragma unroll
    for (int i = 0; i < 4; i++) {
        int row = bm + wm + i * 16 + r0;
#pragma unroll
        for (int j = 0; j < 4; j++) {
            int col = bn + wn + j * 8 + c0 * 2;
            size_t o0 = (size_t)row * DM + col;
            size_t o1 = (size_t)(row + 8) * DM + col;
            float2 v0 = make_float2(acc[i][j][0], acc[i][j][1]);
            float2 v1 = make_float2(acc[i][j][2], acc[i][j][3]);
            if constexpr (MODE == 3) {
                float2 a0 = *(const float2*)(Add + o0);
                float2 a1 = *(const float2*)(Add + o1);
                v0.x += a0.x; v0.y += a0.y;
                v1.x += a1.x; v1.y += a1.y;
            }
            *(float2*)(C + o0) = v0;
            *(float2*)(C + o1) = v1;
        }
    }
}

// ---------------- fused attention: sep = ((r@k^T)*mask) @ v ---------------
// one block per (b,chunk,head); tensor-core fp16, fp32 accum, writes g_att
#define RSTR 72    // halves per row, r/k/v tiles (64 data + 8 pad)
#define SSTR 136   // halves per row, S tile (128 data + 8 pad)
#define ATT_SMEM (3 * 128 * RSTR * 2 + 128 * SSTR * 2)   // 90112 B

__global__ void __launch_bounds__(256, 2) att_kernel(const float* __restrict__ tdcy,
                                                     const float* __restrict__ tfirst)
{
    int bch = blockIdx.x;
    int h = bch & 31;
    int chunk = (bch >> 5) & 15;
    int b = bch >> 9;
    extern __shared__ char smem[];
    __half* rs = (__half*)smem;
    __half* ks = rs + 128 * RSTR;
    __half* vs = ks + 128 * RSTR;
    __half* ss = vs + 128 * RSTR;
    int tid = threadIdx.x, lane = tid & 31, warp = tid >> 5;
    int lane7 = lane & 7;
    int r0 = lane >> 2, c0 = lane & 3;

    // stage r,k,v tiles (fp32 -> fp16)
    size_t gbase = ((size_t)(b * SEQ + chunk * CK)) * DM + h * 64;
#pragma unroll
    for (int q = 0; q < 8; q++) {
        int idx = q * 256 + tid;
        int row = idx >> 4, cc = (idx & 15) * 4;
        size_t off = gbase + (size_t)row * DM + cc;
        float4 rv = *(const float4*)(g_r + off);
        float4 kv = *(const float4*)(g_k + off);
        float4 vv = *(const float4*)(g_v + off);
        __half2* rp = (__half2*)&rs[row * RSTR + cc];
        rp[0] = __floats2half2_rn(rv.x, rv.y); rp[1] = __floats2half2_rn(rv.z, rv.w);
        __half2* kp = (__half2*)&ks[row * RSTR + cc];
        kp[0] = __floats2half2_rn(kv.x, kv.y); kp[1] = __floats2half2_rn(kv.z, kv.w);
        __half2* vp = (__half2*)&vs[row * RSTR + cc];
        vp[0] = __floats2half2_rn(vv.x, vv.y); vp[1] = __floats2half2_rn(vv.z, vv.w);
    }
    __syncthreads();

    // phase 2: S = r @ k^T (warp grid 2x4, warp tile 64x32, K=64)
    int wm = (warp >> 2) * 64, wn = (warp & 3) * 32;
    uint32_t rs_b = smem_u32(rs), ks_b = smem_u32(ks);
    uint32_t vs_b = smem_u32(vs), ss_b = smem_u32(ss);
    uint32_t a_off = rs_b + (uint32_t)(((wm + ((lane >> 3) & 1) * 8 + lane7) * RSTR
                                      + ((lane >> 4) & 1) * 8) * 2);
    uint32_t b_off = ks_b + (uint32_t)(((wn + ((lane >> 4) & 1) * 8 + lane7) * RSTR
                                      + ((lane >> 3) & 1) * 8) * 2);
    float acc[4][4][4];
#pragma unroll
    for (int i = 0; i < 4; i++)
#pragma unroll
        for (int j = 0; j < 4; j++)
#pragma unroll
            for (int e = 0; e < 4; e++) acc[i][j][e] = 0.f;
#pragma unroll
    for (int kb = 0; kb < 4; kb++) {
        unsigned af[4][4], bf[8];
#pragma unroll
        for (int i = 0; i < 4; i++)
            ldsm4(af[i], a_off + i * (16 * RSTR * 2) + kb * 32);
        ldsm4(&bf[0], b_off + kb * 32);
        ldsm4(&bf[4], b_off + 16 * RSTR * 2 + kb * 32);
#pragma unroll
        for (int i = 0; i < 4; i++)
#pragma unroll
            for (int j = 0; j < 4; j++)
                mma_f16(acc[i][j], af[i], &bf[j * 2]);
    }

    // phase 3: apply decay mask (fp32) and store S as fp16
    float logw = -expf(tdcy[h]);
    float u    =  expf(tfirst[h]);
#pragma unroll
    for (int i = 0; i < 4; i++) {
#pragma unroll
        for (int j = 0; j < 4; j++) {
            int ri = wm + i * 16 + r0;
            int cj = wn + j * 8 + c0 * 2;
#pragma unroll
            for (int e = 0; e < 4; e++) {
                int rr = ri + (e >> 1) * 8;
                int cc = cj + (e & 1);
                float m;
                if (rr > cc)       m = expf(logw * (float)(rr - cc - 1));
                else if (rr == cc) m = u;
                else               m = 0.f;
                ss[rr * SSTR + cc] = __float2half(acc[i][j][e] * m);
            }
        }
    }
    __syncthreads();

    // phase 4: O = S @ v (warp grid 2x4, warp tile 64x16, K=128)
    int wm2 = (warp >> 2) * 64, wn2 = (warp & 3) * 16;
    uint32_t a2 = ss_b + (uint32_t)(((wm2 + ((lane >> 3) & 1) * 8 + lane7) * SSTR
                                   + ((lane >> 4) & 1) * 8) * 2);
    uint32_t bt = vs_b + (uint32_t)(((((lane >> 3) & 1) * 8 + lane7) * RSTR
                                   + wn2 + ((lane >> 4) & 1) * 8) * 2);
    float acc2[4][2][4];
#pragma unroll
    for (int i = 0; i < 4; i++)
#pragma unroll
        for (int j = 0; j < 2; j++)
#pragma unroll
            for (int e = 0; e < 4; e++) acc2[i][j][e] = 0.f;
#pragma unroll
    for (int kb = 0; kb < 8; kb++) {
        unsigned af[4][4], bf[4];
#pragma unroll
        for (int i = 0; i < 4; i++)
            ldsm4(af[i], a2 + i * (16 * SSTR * 2) + kb * 32);
        ldsm4t(bf, bt + kb * (16 * RSTR * 2));
#pragma unroll
        for (int i = 0; i < 4; i++)
#pragma unroll
            for (int j = 0; j < 2; j++)
                mma_f16(acc2[i][j], af[i], &bf[j * 2]);
    }
#pragma unroll
    for (int i = 0; i < 4; i++) {
        int row = wm2 + i * 16 + r0;
        size_t o = ((size_t)(b * SEQ + chunk * CK + row)) * DM + h * 64;
#pragma unroll
        for (int j = 0; j < 2; j++) {
            int col = wn2 + j * 8 + c0 * 2;
            *(float2*)(g_att + o + col) = make_float2(acc2[i][j][0], acc2[i][j][1]);
            *(float2*)(g_att + o + (size_t)8 * DM + col) = make_float2(acc2[i][j][2], acc2[i][j][3]);
        }
    }
}

// ---------------- scan decomposition ----------------
__global__ void kv_kernel(const float* __restrict__ tdcy)
{
    int c = blockIdx.x, bh = blockIdx.y;
    int h = bh & 31, b = bh >> 5;
    int tid = threadIdx.x;
    __shared__ float bufA[32][68];
    __shared__ float bufB[32][68];
    float logw = -expf(tdcy[h]);
    int lrow = tid >> 3, lcol = (tid & 7) * 8;
    int td = (tid >> 4) * 4, te2 = (tid & 15) * 4;
    size_t base = ((size_t)(b*SEQ + c*CK)) * DM + h * 64;
    float sacc[4][4] = {};
    for (int s4 = 0; s4 < 4; s4++) {
        int j = s4 * 32 + lrow;
        float wk = expf(logw * (float)(127 - j));
        const float* ksrc = g_k + base + (size_t)j * DM + lcol;
        const float* vsrc = g_v + base + (size_t)j * DM + lcol;
        float4 k0 = *(const float4*)ksrc;
        float4 k1 = *(const float4*)(ksrc + 4);
        float4 w0 = *(const float4*)vsrc;
        float4 w1 = *(const float4*)(vsrc + 4);
        k0.x *= wk; k0.y *= wk; k0.z *= wk; k0.w *= wk;
        k1.x *= wk; k1.y *= wk; k1.z *= wk; k1.w *= wk;
        *(float4*)&bufA[lrow][lcol]     = k0;
        *(float4*)&bufA[lrow][lcol + 4] = k1;
        *(float4*)&bufB[lrow][lcol]     = w0;
        *(float4*)&bufB[lrow][lcol + 4] = w1;
        __syncthreads();
#pragma unroll 4
        for (int jj = 0; jj < 32; jj++) {
            float4 ka = *(const float4*)&bufA[jj][td];
            float4 vb = *(const float4*)&bufB[jj][te2];
            float ar[4] = {ka.x,ka.y,ka.z,ka.w};
            float br[4] = {vb.x,vb.y,vb.z,vb.w};
#pragma unroll
            for (int x = 0; x < 4; x++)
#pragma unroll
                for (int y = 0; y < 4; y++)
                    sacc[x][y] += ar[x] * br[y];
        }
        __syncthreads();
    }
    size_t obase = ((size_t)bh * NC + c) * 4096;
#pragma unroll
    for (int x = 0; x < 4; x++)
#pragma unroll
        for (int y = 0; y < 4; y++)
            g_kv[obase + (size_t)(td + x) * 64 + te2 + y] = sacc[x][y];
}

__global__ void combine_kernel(const float* __restrict__ tdcy,
                               float* __restrict__ state_out)
{
    int bh = blockIdx.x;
    int h = bh & 31;
    int tid = threadIdx.x;
    float wC = expf(-expf(tdcy[h]) * 128.f);
    float st[16];
#pragma unroll
    for (int q = 0; q < 16; q++) st[q] = 0.f;
    size_t base = (size_t)bh * NC * 4096;
    for (int c = 0; c < NC; c++) {
        size_t off = base + (size_t)c * 4096;
#pragma unroll
        for (int q = 0; q < 16; q++) {
            size_t idx = off + q * 256 + tid;
            g_state[idx] = st[q];
            st[q] = st[q] * wC + g_kv[idx];
        }
    }
#pragma unroll
    for (int q = 0; q < 16; q++)
        state_out[(size_t)bh * 4096 + q * 256 + tid] = st[q];
}

__global__ void bias_kernel(const float* __restrict__ tdcy)
{
    int c = blockIdx.x, bh = blockIdx.y;
    int h = bh & 31, b = bh >> 5;
    int tid = threadIdx.x;
    __shared__ float rs[64][132];
    __shared__ float ss[64][68];
    {
        int lrow = tid >> 1, lc = (tid & 1) * 32;
        size_t rbase = ((size_t)(b*SEQ + c*CK + lrow)) * DM + h * 64 + lc;
#pragma unroll
        for (int m = 0; m < 8; m++) {
            float4 rv = *(const float4*)(g_r + rbase + m * 4);
            int d = lc + m * 4;
            rs[d+0][lrow] = rv.x; rs[d+1][lrow] = rv.y;
            rs[d+2][lrow] = rv.z; rs[d+3][lrow] = rv.w;
        }
        size_t sbase = ((size_t)bh * NC + c) * 4096;
#pragma unroll
        for (int q = 0; q < 16; q++) {
            int idx = q * 256 + tid;
            ss[idx >> 6][idx & 63] = g_state[sbase + idx];
        }
    }
    __syncthreads();
    int ty = tid >> 3, tx = tid & 7;
    float acc[4][8] = {};
#pragma unroll 4
    for (int d = 0; d < 64; d++) {
        float4 a  = *(const float4*)&rs[d][ty * 4];
        float4 b0 = *(const float4*)&ss[d][tx * 8];
        float4 b1 = *(const float4*)&ss[d][tx * 8 + 4];
        float ar[4] = {a.x,a.y,a.z,a.w};
        float br[8] = {b0.x,b0.y,b0.z,b0.w,b1.x,b1.y,b1.z,b1.w};
#pragma unroll
        for (int x = 0; x < 4; x++)
#pragma unroll
            for (int e = 0; e < 8; e++)
                acc[x][e] += ar[x] * br[e];
    }
    float logw = -expf(tdcy[h]);
    size_t obase = ((size_t)(b*SEQ + c*CK)) * DM + h * 64;
#pragma unroll
    for (int x = 0; x < 4; x++) {
        int i = ty * 4 + x;
        float wi = expf(logw * (float)i);
        float* dst = g_att + obase + (size_t)i * DM + tx * 8;
        float4 o0 = *(float4*)dst;
        float4 o1 = *(float4*)(dst + 4);
        o0.x += wi * acc[x][0]; o0.y += wi * acc[x][1];
        o0.z += wi * acc[x][2]; o0.w += wi * acc[x][3];
        o1.x += wi * acc[x][4]; o1.y += wi * acc[x][5];
        o1.z += wi * acc[x][6]; o1.w += wi * acc[x][7];
        *(float4*)dst = o0;
        *(float4*)(dst + 4) = o1;
    }
}

// ---------------- per-head LN: g_att (fp32) -> g_atth (fp16) ----------------
__global__ void lnx_kernel(const float* __restrict__ sc,
                           const float* __restrict__ bi)
{
    int w = blockIdx.x * 8 + (threadIdx.x >> 5);
    int lid = threadIdx.x & 31;
    int h = w & 31;
    size_t row = (size_t)(w >> 5);
    const float* p = g_att + row * DM + h * 64;
    __half* po = g_atth + row * DM + h * 64;
    float x0 = p[lid], x1 = p[lid + 32];
    float s = x0 + x1, q = x0 * x0 + x1 * x1;
#pragma unroll
    for (int o = 16; o > 0; o >>= 1) {
        s += __shfl_xor_sync(0xffffffffu, s, o);
        q += __shfl_xor_sync(0xffffffffu, q, o);
    }
    float mu  = s * (1.f / 64.f);
    float inv = rsqrtf(q * (1.f / 64.f) - mu * mu + 1e-5f);
    po[lid]      = __float2half((x0 - mu) * inv * sc[h * 64 + lid]      + bi[h * 64 + lid]);
    po[lid + 32] = __float2half((x1 - mu) * inv * sc[h * 64 + lid + 32] + bi[h * 64 + lid + 32]);
}

// ---------------- launch ----------------
extern "C" void kernel_launch(void* const* d_in, const int* in_sizes, int n_in,
                              void* d_out, int out_size)
{
    const float* inputs = (const float*)d_in[0];
    const float* tmr    = (const float*)d_in[1];
    const float* tmk    = (const float*)d_in[2];
    const float* tmv    = (const float*)d_in[3];
    const float* Wk     = (const float*)d_in[4];
    const float* Wv     = (const float*)d_in[5];
    const float* Wr     = (const float*)d_in[6];
    const float* Wo     = (const float*)d_in[7];
    const float* tdcy   = (const float*)d_in[8];
    const float* tfirst = (const float*)d_in[9];
    const float* ln1s   = (const float*)d_in[10];
    const float* ln1b   = (const float*)d_in[11];
    const float* lnxs   = (const float*)d_in[12];
    const float* lnxb   = (const float*)d_in[13];

    float* out0      = (float*)d_out;
    float* out_xlast = out0 + (size_t)BZ * SEQ * DM;
    float* out_state = out_xlast + (size_t)BZ * DM;

    const int GSMEM = 4 * STG_BYTES;   // 49152 B
    cudaFuncSetAttribute(tgemm_kernel<0>, cudaFuncAttributeMaxDynamicSharedMemorySize, GSMEM);
    cudaFuncSetAttribute(tgemm_kernel<1>, cudaFuncAttributeMaxDynamicSharedMemorySize, GSMEM);
    cudaFuncSetAttribute(tgemm_kernel<2>, cudaFuncAttributeMaxDynamicSharedMemorySize, GSMEM);
    cudaFuncSetAttribute(tgemm_kernel<3>, cudaFuncAttributeMaxDynamicSharedMemorySize, GSMEM);
    cudaFuncSetAttribute(att_kernel,      cudaFuncAttributeMaxDynamicSharedMemorySize, ATT_SMEM);

    __half* wtr; __half* wtk; __half* wtv; __half* wto;
    cudaGetSymbolAddress((void**)&wtr, g_wtr);
    cudaGetSymbolAddress((void**)&wtk, g_wtk);
    cudaGetSymbolAddress((void**)&wtv, g_wtv);
    cudaGetSymbolAddress((void**)&wto, g_wto);

    transpose4_kernel<<<dim3(64, 64, 4), dim3(32, 8)>>>(Wr, wtr, Wk, wtk, Wv, wtv, Wo, wto);
    lnmix_kernel<<<MROWS, 256>>>(inputs, ln1s, ln1b, tmr, tmk, tmv, out_xlast);

    dim3 g(DM / 128, MROWS / 128);
    tgemm_kernel<0><<<g, 256, GSMEM>>>(wtr, nullptr, nullptr);
    tgemm_kernel<1><<<g, 256, GSMEM>>>(wtk, nullptr, nullptr);
    tgemm_kernel<2><<<g, 256, GSMEM>>>(wtv, nullptr, nullptr);
    att_kernel<<<BZ * NC * NH, 256, ATT_SMEM>>>(tdcy, tfirst);
    kv_kernel<<<dim3(NC, BZ * NH), 256>>>(tdcy);
    combine_kernel<<<BZ * NH, 256>>>(tdcy, out_state);
    bias_kernel<<<dim3(NC, BZ * NH), 256>>>(tdcy);
    lnx_kernel<<<(MROWS * NH) / 8, 256>>>(lnxs, lnxb);
    tgemm_kernel<3><<<g, 256, GSMEM>>>(wto, inputs, out0);
}